// round 7
// baseline (speedup 1.0000x reference)
#include <cuda_runtime.h>
#include <cstdint>

#define NTAG      48
#define START_TAG 46
#define STOP_TAG  47
#define BB        128
#define TT        256
#define RS        50                 // padded row stride: matvec LDS covers all 32 banks
#define TILE_ELEMS (NTAG * RS)       // 2400
#define NTHREADS  384                // 12 warps; j = tid>>3, s = tid&7

__device__ float        g_partials[BB];
__device__ unsigned int g_count = 0;

__device__ __forceinline__ float rcp_approx(float x) {
    float y;
    asm("rcp.approx.f32 %0, %1;" : "=f"(y) : "f"(x));
    return y;
}

__global__ void __launch_bounds__(NTHREADS, 1) viterbi_fwd(
    const float* __restrict__ feats,
    const void* __restrict__ targets_raw,
    const void* __restrict__ lengths_raw,
    float* __restrict__ out)
{
    __shared__ __align__(16) float tile[2][TILE_ELEMS];   // exp(feature) tiles
    __shared__ float P[2][NTAG];
    __shared__ float s_inv[2];
    __shared__ float s_q0[TT];
    __shared__ int   s_tgt[TT];
    __shared__ float s_red[NTHREADS];
    __shared__ int   s_isLast;

    const int b   = blockIdx.x;
    const int tid = threadIdx.x;

    // dtype probe: genuine int64 length[0] lies in [1,256]; int32-misread >= 2^32.
    const long long probe = ((const long long*)lengths_raw)[0];
    const bool is64 = (probe >= 1 && probe <= TT);

    int len = is64 ? (int)((const long long*)lengths_raw)[b]
                   : ((const int*)lengths_raw)[b];
    if (len < 1)  len = 1;
    if (len > TT) len = TT;
    const float* fb = feats + (size_t)b * TT * (NTAG * NTAG);

    for (int c = tid; c < TT; c += NTHREADS) {
        int v = is64 ? (int)((const long long*)targets_raw)[(size_t)b * TT + c]
                     : ((const int*)targets_raw)[(size_t)b * TT + c];
        if (v < 0) v = 0;
        if (v >= NTAG * NTAG) v = NTAG * NTAG - 1;
        s_tgt[c] = v;
    }

    // Per-thread element slice: 6 contiguous floats, never crossing a row.
    const int e0   = tid * 6;
    const int erow = e0 / NTAG;
    const int ecol = e0 % NTAG;
    float* stsA = &tile[0][erow * RS + ecol];
    float* stsB = &tile[1][erow * RS + ecol];

    float goldAcc = 0.0f;
    float X0[6], X1[6], X2[6];             // 3-deep register tile ring (tile# mod 3)

#define LDG6(R, T)  do {                                                     \
        const float2* _g = (const float2*)(fb + (size_t)(T) * (NTAG*NTAG) + e0); \
        float2 _a = _g[0], _b = _g[1], _c = _g[2];                           \
        (R)[0] = _a.x; (R)[1] = _a.y; (R)[2] = _b.x;                         \
        (R)[3] = _b.y; (R)[4] = _c.x; (R)[5] = _c.y;                         \
    } while (0)

    // ---- prologue: LDG tiles 1..3 into ring slots 1,2,0 ----
    if (len > 1) LDG6(X1, 1);
    if (len > 2) LDG6(X2, 2);
    if (len > 3) LDG6(X0, 3);

    // P_0[j] = exp(features[b,0,START,j]); q0[0] on tid 0.
    if (tid < NTAG) {
        const float p = __expf(fb[START_TAG * NTAG + tid]);
        P[0][tid] = p;
        if (tid == 0) {
            s_inv[1] = rcp_approx(p);
            s_q0[0]  = p;
        }
    }
    __syncthreads();   // s_tgt visible
    if (tid == 0) goldAcc += fb[s_tgt[0]];

    // convert tile 1 (X1) -> smem tile[1]
    if (len > 1) {
        const int tg = s_tgt[1] - e0;
        #pragma unroll
        for (int k = 0; k < 6; ++k) {
            const float v = X1[k];
            if (k == tg) goldAcc += v;
            stsB[k] = __expf(v);
        }
    }
    __syncthreads();

    const int j = tid >> 3;                // destination tag
    const int s = tid & 7;                 // source slice (6 rows)
    const int co = (s * 6) * RS + j;       // matvec base offset into a tile

    // One recurrence step. RL: ring slot receiving tile T+3 (slot T%3).
    // RC: ring slot holding tile T+1 (slot (T+1)%3), converted this step.
#define STEP(T, RL, RC) do {                                                  \
        if ((T) + 3 < len) LDG6(RL, (T) + 3);                                 \
        const float* E   = &tile[(T) & 1][co];                                \
        const float* Pc  = &P[((T) + 1) & 1][s * 6];                          \
        const float  inv = s_inv[(T) & 1];                                    \
        /* issue matvec loads first (latency overlapped by the convert) */    \
        float er0 = E[0*RS], er1 = E[1*RS], er2 = E[2*RS];                    \
        float er3 = E[3*RS], er4 = E[4*RS], er5 = E[5*RS];                    \
        float pr0 = Pc[0], pr1 = Pc[1], pr2 = Pc[2];                          \
        float pr3 = Pc[3], pr4 = Pc[4], pr5 = Pc[5];                          \
        if ((T) + 1 < len) {                                                  \
            float* _sts = (((T) + 1) & 1) ? stsB : stsA;                      \
            const int _tg = s_tgt[(T) + 1] - e0;                              \
            _Pragma("unroll")                                                 \
            for (int k = 0; k < 6; ++k) {                                     \
                const float v = (RC)[k];                                      \
                if (k == _tg) goldAcc += v;                                   \
                _sts[k] = __expf(v);                                          \
            }                                                                 \
        }                                                                     \
        float acc0 = er0 * pr0 + er1 * pr1 + er2 * pr2;                       \
        float acc1 = er3 * pr3 + er4 * pr4 + er5 * pr5;                       \
        float acc  = (acc0 + acc1) * inv;                                     \
        acc += __shfl_xor_sync(0xffffffffu, acc, 1);                          \
        acc += __shfl_xor_sync(0xffffffffu, acc, 2);                          \
        acc += __shfl_xor_sync(0xffffffffu, acc, 4);                          \
        if (s == 0) P[(T) & 1][j] = acc;                                      \
        if (tid == 0) {                                                       \
            s_inv[((T) + 1) & 1] = rcp_approx(acc);                           \
            s_q0[(T)] = acc;                                                  \
        }                                                                     \
        __syncthreads();                                                      \
    } while (0)

    // 3-phase loop keeps ring indices static (no dynamic register indexing).
    int t = 1;
    while (t < len) {
        STEP(t, X1, X2); ++t; if (t >= len) break;
        STEP(t, X2, X0); ++t; if (t >= len) break;
        STEP(t, X0, X1); ++t;
    }

    // ---- epilogue: parallel logs + gold, fixed-order reduction ----
    float lg = 0.0f;
    if (tid < len - 1) lg = __logf(s_q0[tid]);
    s_red[tid] = lg - goldAcc;
    __syncthreads();
    if (tid < 128) s_red[tid] += s_red[tid + 128] + s_red[tid + 256];
    __syncthreads();
    #pragma unroll
    for (int st = 64; st > 0; st >>= 1) {
        if (tid < st) s_red[tid] += s_red[tid + st];
        __syncthreads();
    }

    if (tid == 0) {
        const float val = s_red[0] + __logf(P[(len - 1) & 1][STOP_TAG]);
        g_partials[b] = val;
        __threadfence();
        const unsigned done = atomicAdd(&g_count, 1);
        s_isLast = (done == BB - 1) ? 1 : 0;
    }
    __syncthreads();

    // Last CTA reduces the 128 partials (fixed tree -> deterministic).
    if (s_isLast) {
        if (tid < BB) s_red[tid] = g_partials[tid];
        __syncthreads();
        #pragma unroll
        for (int st = BB / 2; st > 0; st >>= 1) {
            if (tid < st) s_red[tid] += s_red[tid + st];
            __syncthreads();
        }
        if (tid == 0) {
            out[0] = s_red[0];
            g_count = 0;                   // reset for next graph replay
        }
    }
}

extern "C" void kernel_launch(void* const* d_in, const int* in_sizes, int n_in,
                              void* d_out, int out_size) {
    const float* feats   = nullptr;
    const void*  targets = nullptr;
    const void*  lengths = nullptr;
    for (int i = 0; i < n_in; ++i) {
        if (in_sizes[i] == BB * TT * NTAG * NTAG) feats   = (const float*)d_in[i];
        else if (in_sizes[i] == BB * TT)          targets = d_in[i];
        else if (in_sizes[i] == BB)               lengths = d_in[i];
    }
    viterbi_fwd<<<BB, NTHREADS>>>(feats, targets, lengths, (float*)d_out);
}

// round 8
// speedup vs baseline: 1.1335x; 1.1335x over previous
#include <cuda_runtime.h>
#include <cstdint>

#define NTAG      48
#define START_TAG 46
#define STOP_TAG  47
#define BB        128
#define TT        256
#define RS        50                 // padded row stride: matvec LDS covers all 32 banks
#define TILE_ELEMS (NTAG * RS)       // 2400
#define NTHREADS  384                // 12 warps; j = tid>>3, s = tid&7

__device__ float        g_partials[BB];
__device__ unsigned int g_count = 0;

__device__ __forceinline__ float rcp_approx(float x) {
    float y;
    asm("rcp.approx.f32 %0, %1;" : "=f"(y) : "f"(x));
    return y;
}

__global__ void __launch_bounds__(NTHREADS, 1) viterbi_fwd(
    const float* __restrict__ feats,
    const void* __restrict__ targets_raw,
    const void* __restrict__ lengths_raw,
    float* __restrict__ out)
{
    __shared__ __align__(16) float tile[2][TILE_ELEMS];   // exp(feature) tiles
    __shared__ float P[2][NTAG];
    __shared__ float s_inv[2];
    __shared__ float s_q0[TT];
    __shared__ int   s_tgt[TT];
    __shared__ float s_red[NTHREADS];
    __shared__ int   s_isLast;

    const int b   = blockIdx.x;
    const int tid = threadIdx.x;

    // dtype probe: genuine int64 length[0] lies in [1,256]; int32-misread >= 2^32.
    const long long probe = ((const long long*)lengths_raw)[0];
    const bool is64 = (probe >= 1 && probe <= TT);

    int len = is64 ? (int)((const long long*)lengths_raw)[b]
                   : ((const int*)lengths_raw)[b];
    if (len < 1)  len = 1;
    if (len > TT) len = TT;
    const float* fb = feats + (size_t)b * TT * (NTAG * NTAG);

    for (int c = tid; c < TT; c += NTHREADS) {
        int v = is64 ? (int)((const long long*)targets_raw)[(size_t)b * TT + c]
                     : ((const int*)targets_raw)[(size_t)b * TT + c];
        if (v < 0) v = 0;
        if (v >= NTAG * NTAG) v = NTAG * NTAG - 1;
        s_tgt[c] = v;
    }

    // Per-thread element slice: 6 contiguous floats, never crossing a row.
    const int e0   = tid * 6;
    const int erow = e0 / NTAG;
    const int ecol = e0 % NTAG;
    float* stsA = &tile[0][erow * RS + ecol];
    float* stsB = &tile[1][erow * RS + ecol];

    float goldAcc = 0.0f;
    float r[2][6];                         // register tile buffers (slot = tile# & 1)

#define LDG6(R, T)  do {                                                         \
        const float2* _g = (const float2*)(fb + (size_t)(T) * (NTAG*NTAG) + e0); \
        float2 _a = _g[0], _b = _g[1], _c = _g[2];                               \
        (R)[0] = _a.x; (R)[1] = _a.y; (R)[2] = _b.x;                             \
        (R)[3] = _b.y; (R)[4] = _c.x; (R)[5] = _c.y;                             \
    } while (0)

    // ---- prologue ----
    if (len > 1) LDG6(r[1], 1);            // tile 1 -> slot 1
    if (len > 2) LDG6(r[0], 2);            // tile 2 -> slot 0

    // P_0[j] = exp(features[b,0,START,j]); q0[0] on tid 0.
    if (tid < NTAG) {
        const float p = __expf(fb[START_TAG * NTAG + tid]);
        P[0][tid] = p;
        if (tid == 0) {
            s_inv[1] = rcp_approx(p);
            s_q0[0]  = p;
        }
    }
    __syncthreads();   // s_tgt visible
    if (tid == 0) goldAcc += fb[s_tgt[0]];

    // convert tile 1 (slot 1) -> smem tile[1], then refill slot 1 with tile 3.
    if (len > 1) {
        const int tg = s_tgt[1] - e0;
        #pragma unroll
        for (int k = 0; k < 6; ++k) {
            const float v = r[1][k];
            if (k == tg) goldAcc += v;
            stsB[k] = __expf(v);
        }
    }
    if (len > 3) LDG6(r[1], 3);            // tile 3 -> slot 1 (consumed at t=2)
    __syncthreads();

    const int j = tid >> 3;                // destination tag
    const int s = tid & 7;                 // source slice (6 rows)
    const int co = (s * 6) * RS + j;       // matvec base offset into a tile

    #pragma unroll 2
    for (int t = 1; t < len; ++t) {
        // issue matvec loads first (latency overlapped by the convert below)
        const float* E   = &tile[t & 1][co];
        const float* Pc  = &P[(t + 1) & 1][s * 6];
        const float  inv = s_inv[t & 1];
        float er0 = E[0*RS], er1 = E[1*RS], er2 = E[2*RS];
        float er3 = E[3*RS], er4 = E[4*RS], er5 = E[5*RS];
        float pr0 = Pc[0], pr1 = Pc[1], pr2 = Pc[2];
        float pr3 = Pc[3], pr4 = Pc[4], pr5 = Pc[5];

        // convert tile t+1 (slot (t+1)&1, loaded 2 steps ago) -> smem
        if (t + 1 < len) {
            float* sts = ((t + 1) & 1) ? stsB : stsA;
            const int tg = s_tgt[t + 1] - e0;
            #pragma unroll
            for (int k = 0; k < 6; ++k) {
                const float v = r[(t + 1) & 1][k];
                if (k == tg) goldAcc += v;
                sts[k] = __expf(v);
            }
        }
        // refill the just-consumed slot with tile t+3 (consumed at step t+2)
        if (t + 3 < len) LDG6(r[(t + 1) & 1], t + 3);

        // matvec chain: q_j = inv * sum_i exp(feat)_{i,j} * P[i]
        float acc0 = er0 * pr0 + er1 * pr1 + er2 * pr2;
        float acc1 = er3 * pr3 + er4 * pr4 + er5 * pr5;
        float acc  = (acc0 + acc1) * inv;
        acc += __shfl_xor_sync(0xffffffffu, acc, 1);
        acc += __shfl_xor_sync(0xffffffffu, acc, 2);
        acc += __shfl_xor_sync(0xffffffffu, acc, 4);

        if (s == 0) P[t & 1][j] = acc;
        if (tid == 0) {                    // j==0 group: acc == q_0
            s_inv[(t + 1) & 1] = rcp_approx(acc);
            s_q0[t] = acc;                 // logged in parallel at the end
        }
        __syncthreads();
    }

    // ---- epilogue: parallel logs + gold, fixed-order reduction ----
    float lg = 0.0f;
    if (tid < len - 1) lg = __logf(s_q0[tid]);
    s_red[tid] = lg - goldAcc;
    __syncthreads();
    if (tid < 128) s_red[tid] += s_red[tid + 128] + s_red[tid + 256];
    __syncthreads();
    #pragma unroll
    for (int st = 64; st > 0; st >>= 1) {
        if (tid < st) s_red[tid] += s_red[tid + st];
        __syncthreads();
    }

    if (tid == 0) {
        const float val = s_red[0] + __logf(P[(len - 1) & 1][STOP_TAG]);
        g_partials[b] = val;
        __threadfence();
        const unsigned done = atomicAdd(&g_count, 1);
        s_isLast = (done == BB - 1) ? 1 : 0;
    }
    __syncthreads();

    // Last CTA reduces the 128 partials (fixed tree -> deterministic).
    if (s_isLast) {
        if (tid < BB) s_red[tid] = g_partials[tid];
        __syncthreads();
        #pragma unroll
        for (int st = BB / 2; st > 0; st >>= 1) {
            if (tid < st) s_red[tid] += s_red[tid + st];
            __syncthreads();
        }
        if (tid == 0) {
            out[0] = s_red[0];
            g_count = 0;                   // reset for next graph replay
        }
    }
}

extern "C" void kernel_launch(void* const* d_in, const int* in_sizes, int n_in,
                              void* d_out, int out_size) {
    const float* feats   = nullptr;
    const void*  targets = nullptr;
    const void*  lengths = nullptr;
    for (int i = 0; i < n_in; ++i) {
        if (in_sizes[i] == BB * TT * NTAG * NTAG) feats   = (const float*)d_in[i];
        else if (in_sizes[i] == BB * TT)          targets = d_in[i];
        else if (in_sizes[i] == BB)               lengths = d_in[i];
    }
    viterbi_fwd<<<BB, NTHREADS>>>(feats, targets, lengths, (float*)d_out);
}

// round 9
// speedup vs baseline: 1.4452x; 1.2750x over previous
#include <cuda_runtime.h>
#include <cstdint>

#define NTAG      48
#define START_TAG 46
#define STOP_TAG  47
#define BB        128
#define TT        256
#define RS        50                 // padded row stride: matvec LDS covers all 32 banks
#define TILE_ELEMS (NTAG * RS)       // 2400
#define NBUF      8                  // raw-tile ring (cp.async), 3-step load distance
#define NTHREADS  384                // 12 warps; j = tid>>3, s = tid&7

// dynamic smem: tiles | P[2][48] | s_inv[2] | s_q0[256] | s_tgt[256] | s_red[384] | isLast
#define SMEM_FLOATS (NBUF * TILE_ELEMS + 96 + 2 + TT + TT + NTHREADS + 4)
#define SMEM_BYTES  (SMEM_FLOATS * 4)

__device__ float        g_partials[BB];
__device__ unsigned int g_count = 0;

__device__ __forceinline__ float rcp_approx(float x) {
    float y;
    asm("rcp.approx.f32 %0, %1;" : "=f"(y) : "f"(x));
    return y;
}
__device__ __forceinline__ void cp_async8(uint32_t dst, const void* src) {
    unsigned long long gsrc;
    asm volatile("cvta.to.global.u64 %0, %1;\n" : "=l"(gsrc) : "l"(src));
    asm volatile("cp.async.ca.shared.global [%0], [%1], 8;\n" :: "r"(dst), "l"(gsrc));
}
__device__ __forceinline__ void cp_commit() {
    asm volatile("cp.async.commit_group;\n" ::: "memory");
}
__device__ __forceinline__ void cp_wait3() {
    asm volatile("cp.async.wait_group 3;\n" ::: "memory");
}

// 48x48 f32 tile (192B rows) -> padded SMEM (200B stride). 3 x 8B per thread.
__device__ __forceinline__ void load_tile(uint32_t sbase, const float* g, int tid) {
    const int r0   = tid / 24;
    const int off8 = (tid % 24) * 8;
    #pragma unroll
    for (int it = 0; it < 3; ++it) {
        const int row = r0 + 16 * it;
        cp_async8(sbase + (uint32_t)(row * (RS * 4) + off8),
                  (const char*)g + row * (NTAG * 4) + off8);
    }
}

__global__ void __launch_bounds__(NTHREADS, 1) viterbi_fwd(
    const float* __restrict__ feats,
    const void* __restrict__ targets_raw,
    const void* __restrict__ lengths_raw,
    float* __restrict__ out)
{
    extern __shared__ __align__(16) float smem[];
    float* tiles    = smem;                       // NBUF * TILE_ELEMS (raw features)
    float* P        = smem + NBUF * TILE_ELEMS;   // 2 * 48
    float* s_inv    = P + 96;                     // 2
    float* s_q0     = s_inv + 2;                  // 256
    int*   s_tgt    = (int*)(s_q0 + TT);          // 256
    float* s_red    = (float*)(s_tgt + TT);       // 384
    int*   s_isLast = (int*)(s_red + NTHREADS);

    const int b   = blockIdx.x;
    const int tid = threadIdx.x;

    // dtype probe: genuine int64 length[0] lies in [1,256]; int32-misread >= 2^32.
    const long long probe = ((const long long*)lengths_raw)[0];
    const bool is64 = (probe >= 1 && probe <= TT);

    int len = is64 ? (int)((const long long*)lengths_raw)[b]
                   : ((const int*)lengths_raw)[b];
    if (len < 1)  len = 1;
    if (len > TT) len = TT;
    const float* fb = feats + (size_t)b * TT * (NTAG * NTAG);

    const uint32_t tbase0 = (uint32_t)__cvta_generic_to_shared(tiles);

    for (int c = tid; c < TT; c += NTHREADS) {
        int v = is64 ? (int)((const long long*)targets_raw)[(size_t)b * TT + c]
                     : ((const int*)targets_raw)[(size_t)b * TT + c];
        if (v < 0) v = 0;
        if (v >= NTAG * NTAG) v = NTAG * NTAG - 1;
        s_tgt[c] = v;
    }

    // ---- prologue: commit tiles 0..3 (one group each; empty if past end) ----
    #pragma unroll
    for (int p = 0; p < 4; ++p) {
        if (p < len)
            load_tile(tbase0 + (uint32_t)(p * TILE_ELEMS * 4),
                      fb + (size_t)p * (NTAG * NTAG), tid);
        cp_commit();
    }
    cp_wait3();                 // tile 0 resident
    __syncthreads();            // visibility of tile 0 + s_tgt

    // init: P_0[j] = exp(raw tile0[START,:]); gold t=0; scale for t=1.
    if (tid < NTAG) {
        const float p = __expf(tiles[START_TAG * RS + tid]);
        P[tid] = p;
        if (tid == 0) {
            s_inv[1] = rcp_approx(p);
            s_q0[0]  = p;
        }
    }
    float goldAcc = 0.0f;
    if (tid == 0) {
        const int tg = s_tgt[0];
        goldAcc = tiles[(tg / NTAG) * RS + (tg % NTAG)];
    }
    // NOTE: no barrier needed here; step t=1 starts with wait+bar below.

    const int j = tid >> 3;                 // destination tag
    const int s = tid & 7;                  // source slice (6 rows)
    const int co = (s * 6) * RS + j;        // matvec base offset into a tile

    #pragma unroll 2
    for (int t = 1; t < len; ++t) {
        // one commit per step: tile t+3 (or empty), then constant wait 3
        if (t + 3 < len)
            load_tile(tbase0 + (uint32_t)(((t + 3) & (NBUF - 1)) * TILE_ELEMS * 4),
                      fb + (size_t)(t + 3) * (NTAG * NTAG), tid);
        cp_commit();
        cp_wait3();             // all groups except the 3 newest done -> tile t resident
        __syncthreads();        // cp.async visibility + P/s_inv publication

        const float* E   = tiles + (size_t)(t & (NBUF - 1)) * TILE_ELEMS + co;
        const float* Pc  = P + ((t + 1) & 1) * NTAG + s * 6;
        const float  inv = s_inv[t & 1];

        // raw loads -> exp inline -> FMA tree (convert stage eliminated)
        const float w0 = __expf(E[0 * RS]);
        const float w1 = __expf(E[1 * RS]);
        const float w2 = __expf(E[2 * RS]);
        const float w3 = __expf(E[3 * RS]);
        const float w4 = __expf(E[4 * RS]);
        const float w5 = __expf(E[5 * RS]);

        float acc0 = w0 * Pc[0] + w1 * Pc[1] + w2 * Pc[2];
        float acc1 = w3 * Pc[3] + w4 * Pc[4] + w5 * Pc[5];
        float acc  = (acc0 + acc1) * inv;
        acc += __shfl_xor_sync(0xffffffffu, acc, 1);
        acc += __shfl_xor_sync(0xffffffffu, acc, 2);
        acc += __shfl_xor_sync(0xffffffffu, acc, 4);

        if (s == 0) P[(t & 1) * NTAG + j] = acc;
        if (tid == 0) {                     // j==0 group: acc == q_0
            s_inv[(t + 1) & 1] = rcp_approx(acc);
            s_q0[t] = acc;                  // logged in parallel at the end
            const int tg = s_tgt[t];        // gold from the raw tile (resident)
            goldAcc += tiles[(size_t)(t & (NBUF - 1)) * TILE_ELEMS
                             + (tg / NTAG) * RS + (tg % NTAG)];
        }
    }
    __syncthreads();            // last P / s_q0 published

    // ---- epilogue: parallel logs + gold, fixed-order reduction ----
    float lg = 0.0f;
    if (tid < len - 1) lg = __logf(s_q0[tid]);
    s_red[tid] = lg - goldAcc;
    __syncthreads();
    if (tid < 128) s_red[tid] += s_red[tid + 128] + s_red[tid + 256];
    __syncthreads();
    #pragma unroll
    for (int st = 64; st > 0; st >>= 1) {
        if (tid < st) s_red[tid] += s_red[tid + st];
        __syncthreads();
    }

    if (tid == 0) {
        const float val = s_red[0] + __logf(P[((len - 1) & 1) * NTAG + STOP_TAG]);
        g_partials[b] = val;
        __threadfence();
        const unsigned done = atomicAdd(&g_count, 1);
        s_isLast[0] = (done == BB - 1) ? 1 : 0;
    }
    __syncthreads();

    // Last CTA reduces the 128 partials (fixed tree -> deterministic).
    if (s_isLast[0]) {
        if (tid < BB) s_red[tid] = g_partials[tid];
        __syncthreads();
        #pragma unroll
        for (int st = BB / 2; st > 0; st >>= 1) {
            if (tid < st) s_red[tid] += s_red[tid + st];
            __syncthreads();
        }
        if (tid == 0) {
            out[0] = s_red[0];
            g_count = 0;                    // reset for next graph replay
        }
    }
}

extern "C" void kernel_launch(void* const* d_in, const int* in_sizes, int n_in,
                              void* d_out, int out_size) {
    const float* feats   = nullptr;
    const void*  targets = nullptr;
    const void*  lengths = nullptr;
    for (int i = 0; i < n_in; ++i) {
        if (in_sizes[i] == BB * TT * NTAG * NTAG) feats   = (const float*)d_in[i];
        else if (in_sizes[i] == BB * TT)          targets = d_in[i];
        else if (in_sizes[i] == BB)               lengths = d_in[i];
    }
    cudaFuncSetAttribute(viterbi_fwd,
                         cudaFuncAttributeMaxDynamicSharedMemorySize, SMEM_BYTES);
    viterbi_fwd<<<BB, NTHREADS, SMEM_BYTES>>>(feats, targets, lengths, (float*)d_out);
}